// round 13
// baseline (speedup 1.0000x reference)
#include <cuda_runtime.h>
#include <cuda_bf16.h>
#include <cstdint>
#include <math.h>

#define NBATCH 256
#define MG     256
#define NTOT   (NBATCH*MG)      // 65536 nodes
#define KNN    15
#define FIN    7
#define CC     128
#define PST    384
#define C2     768
#define LEAKY  0.01f
#define AGG_NORM (1.0f/15.0f)

// ---------------- scratch ------------------------------------------------------
__device__ int   g_knn[NTOT*KNN];
__device__ float g_P[(size_t)NTOT*PST];
__device__ __nv_bfloat16 g_hhi[(size_t)NTOT*CC];
__device__ __nv_bfloat16 g_hlo[(size_t)NTOT*CC];
__device__ float g_pool[NBATCH*C2];
__device__ float g_gf[NBATCH*C2];
__device__ float g_part[4*NBATCH*C2];
__device__ __nv_bfloat16 g_ghiA[NBATCH*C2], g_gloA[NBATCH*C2];
__device__ __nv_bfloat16 g_ghiB[NBATCH*C2], g_gloB[NBATCH*C2];
__device__ __nv_bfloat16 g_WctHi[2*3*CC*CC], g_WctLo[2*3*CC*CC];
__device__ __nv_bfloat16 g_WmtHi[5*C2*C2],   g_WmtLo[5*C2*C2];

// ---------------- helpers -------------------------------------------------------
__device__ __forceinline__ uint32_t smem_u32(const void* p) {
    uint32_t a;
    asm("{ .reg .u64 t; cvta.to.shared.u64 t, %1; cvt.u32.u64 %0, t; }" : "=r"(a) : "l"(p));
    return a;
}
__device__ __forceinline__ void ldm_x4(uint32_t* r, uint32_t addr) {
    asm volatile("ldmatrix.sync.aligned.m8n8.x4.shared.b16 {%0,%1,%2,%3}, [%4];"
                 : "=r"(r[0]), "=r"(r[1]), "=r"(r[2]), "=r"(r[3]) : "r"(addr));
}
__device__ __forceinline__ void ldm_x2(uint32_t* r, uint32_t addr) {
    asm volatile("ldmatrix.sync.aligned.m8n8.x2.shared.b16 {%0,%1}, [%2];"
                 : "=r"(r[0]), "=r"(r[1]) : "r"(addr));
}
__device__ __forceinline__ void mma16816(float* c, const uint32_t* a, const uint32_t* b) {
    asm volatile("mma.sync.aligned.m16n8k16.row.col.f32.bf16.bf16.f32 "
        "{%0,%1,%2,%3}, {%4,%5,%6,%7}, {%8,%9}, {%0,%1,%2,%3};"
        : "+f"(c[0]), "+f"(c[1]), "+f"(c[2]), "+f"(c[3])
        : "r"(a[0]), "r"(a[1]), "r"(a[2]), "r"(a[3]), "r"(b[0]), "r"(b[1]));
}
__device__ __forceinline__ void cpa16(uint32_t dst, const void* src) {
    asm volatile("cp.async.ca.shared.global [%0], [%1], 16;" :: "r"(dst), "l"(src));
}
__device__ __forceinline__ void cpa_commit() { asm volatile("cp.async.commit_group;"); }
__device__ __forceinline__ void cpa_wait1()  { asm volatile("cp.async.wait_group 1;"); }
__device__ __forceinline__ void cpa_wait0()  { asm volatile("cp.async.wait_group 0;"); }

// ---------------- kNN: warp per node, warp-argmin top-15 ---------------------------
__global__ void __launch_bounds__(256)
knn_kernel(const float* __restrict__ x, int* __restrict__ knn) {
    __shared__ float4 pos[MG];
    __shared__ float  sq[MG];
    const int g    = blockIdx.y;
    const int nb   = blockIdx.x;
    const int tid  = threadIdx.x;
    const int w    = tid >> 5;
    const int lane = tid & 31;

    {
        const float* xr = x + (size_t)(g*MG + tid)*FIN;
        float4 p = make_float4(xr[0], xr[1], xr[2], xr[3]);
        pos[tid] = p;
        sq[tid]  = p.x*p.x + p.y*p.y + p.z*p.z + p.w*p.w;
    }
    __syncthreads();

    const int n = nb*8 + w;
    const float4 p = pos[n];
    const float mysq = sq[n];
    const int jbase = lane*8;
    float d[8];
#pragma unroll
    for (int i = 0; i < 8; i++) {
        int j = jbase + i;
        float4 q = pos[j];
        float dd = mysq + sq[j] - 2.0f*(p.x*q.x + p.y*q.y + p.z*q.z + p.w*q.w);
        d[i] = (j == n) ? 1e30f : dd;
    }

    int* out = knn + (size_t)(g*MG + n)*KNN;
#pragma unroll 1
    for (int it = 0; it < KNN; it++) {
        float bv = d[0]; int bi = 0;
#pragma unroll
        for (int i = 1; i < 8; i++) if (d[i] < bv) { bv = d[i]; bi = i; }
        float v = bv; int j = jbase + bi;
#pragma unroll
        for (int o = 16; o; o >>= 1) {
            float v2 = __shfl_xor_sync(0xffffffff, v, o);
            int   j2 = __shfl_xor_sync(0xffffffff, j, o);
            if (v2 < v || (v2 == v && j2 < j)) { v = v2; j = j2; }
        }
        if (lane == (j >> 3)) {
            int slot = j & 7;
#pragma unroll
            for (int i = 0; i < 8; i++) if (i == slot) d[i] = 1e30f;
        }
        if (lane == 0) out[it] = g*MG + j;
    }
}

// ---------------- weight prep ---------------------------------------------------
struct Ptr2 { const float* p[2]; };
struct Ptr5 { const float* p[5]; };
__global__ void wprep_conv_all(Ptr2 Ws, __nv_bfloat16* __restrict__ hi,
                               __nv_bfloat16* __restrict__ lo) {
    int idx = blockIdx.x*256 + threadIdx.x;
    if (idx >= 2*3*CC*CC) return;
    int l = idx / (3*CC*CC), r0 = idx % (3*CC*CC);
    int s = r0 / (CC*CC), r = r0 % (CC*CC), n = r / CC, k = r % CC;
    float v = Ws.p[l][(s*CC + k)*CC + n];
    __nv_bfloat16 h = __float2bfloat16(v);
    hi[idx] = h; lo[idx] = __float2bfloat16(v - __bfloat162float(h));
}
__global__ void wprep_mlp_all(Ptr5 Ws, __nv_bfloat16* __restrict__ hi,
                              __nv_bfloat16* __restrict__ lo) {
    int idx = blockIdx.x*256 + threadIdx.x;
    if (idx >= 5*C2*C2) return;
    int i = idx / (C2*C2), r = idx % (C2*C2), n = r / C2, k = r % C2;
    float v = Ws.p[i][k*C2 + n];
    __nv_bfloat16 h = __float2bfloat16(v);
    hi[idx] = h; lo[idx] = __float2bfloat16(v - __bfloat162float(h));
}

// ---------------- fused TAGConv aggregate + activate + pool (float2 gathers) ---------
// 512 threads = 16 warps. lane: c2 = lane&15 (channel pair), sub = lane>>4.
// Thread handles 8 nodes (w*16 + j*2 + sub), one float2 channel-pair each.
// smem bytes: s2 [0,32768) | st [32768,65536) | nb16 [65536,73216) | xs [73216,+8192) L1
#define AGG_THREADS 512
#define AGG_SMEM_MAIN 73216
#define AGG_SMEM_L1   (AGG_SMEM_MAIN + 8192)
template<bool L1>
__global__ void __launch_bounds__(AGG_THREADS)
tag_agg(const float* __restrict__ P, const float* __restrict__ x,
        const float* __restrict__ Wc, const int* __restrict__ knn,
        const float* __restrict__ bias,
        __nv_bfloat16* __restrict__ hhi, __nv_bfloat16* __restrict__ hlo,
        float* __restrict__ g, int layer) {
    extern __shared__ char smb[];
    float*    s2   = (float*)smb;
    float*    st   = (float*)(smb + 32768);
    uint16_t* nb16 = (uint16_t*)(smb + 65536);
    float*    xs   = (float*)(smb + 73216);

    const int c0   = blockIdx.x*32;
    const int gph  = blockIdx.y;
    const int base = gph*MG;
    const int tid  = threadIdx.x;
    const int w    = tid >> 5;
    const int lane = tid & 31;
    const int c2   = lane & 15;
    const int sub  = lane >> 4;
    const int cc   = c2*2;

    // neighbor row byte-offsets (node_local * 128 bytes)
    for (int i = tid; i < MG*KNN; i += AGG_THREADS)
        nb16[i] = (uint16_t)((knn[(size_t)base*KNN + i] & (MG-1)) << 7);

    if (L1) {
        for (int i = tid; i < MG*FIN; i += AGG_THREADS)
            xs[(i/FIN)*8 + (i%FIN)] = x[(size_t)base*FIN + i];
    }

    // ---- stage s2 = P2 chunk ----
    if (L1) {
        __syncthreads();   // xs ready
        float2 w2v[FIN];
#pragma unroll
        for (int f = 0; f < FIN; f++)
            w2v[f] = *(const float2*)&Wc[(2*FIN + f)*CC + c0 + cc];
#pragma unroll
        for (int j = 0; j < 8; j++) {
            int n = w*16 + j*2 + sub;
            float2 a = make_float2(0.f, 0.f);
#pragma unroll
            for (int f = 0; f < FIN; f++) {
                float xv = xs[n*8 + f];
                a.x += xv*w2v[f].x; a.y += xv*w2v[f].y;
            }
            *(float2*)&s2[n*32 + cc] = a;
        }
    } else {
#pragma unroll
        for (int j = 0; j < 8; j++) {
            int n = w*16 + j*2 + sub;
            *(float2*)&s2[n*32 + cc] =
                *(const float2*)&P[(size_t)(base + n)*PST + 256 + c0 + cc];
        }
    }
    __syncthreads();

    const char* s2b = (const char*)s2 + c2*8;
    const char* stb = (const char*)st + c2*8;

    // ---- pass 1: t = P1 + A*P2 ----
    {
        float2 w1v[FIN];
        if (L1) {
#pragma unroll
            for (int f = 0; f < FIN; f++)
                w1v[f] = *(const float2*)&Wc[(1*FIN + f)*CC + c0 + cc];
        }
#pragma unroll
        for (int j = 0; j < 8; j++) {
            int n = w*16 + j*2 + sub;
            const uint16_t* nbp = nb16 + n*KNN;
            float2 sa = make_float2(0.f, 0.f), sb = make_float2(0.f, 0.f);
#pragma unroll
            for (int k = 0; k < 14; k += 2) {
                float2 va = *(const float2*)(s2b + nbp[k]);
                float2 vb = *(const float2*)(s2b + nbp[k+1]);
                sa.x += va.x; sa.y += va.y;
                sb.x += vb.x; sb.y += vb.y;
            }
            {
                float2 va = *(const float2*)(s2b + nbp[14]);
                sa.x += va.x; sa.y += va.y;
            }
            float2 p1;
            if (L1) {
                p1 = make_float2(0.f, 0.f);
#pragma unroll
                for (int f = 0; f < FIN; f++) {
                    float xv = xs[n*8 + f];
                    p1.x += xv*w1v[f].x; p1.y += xv*w1v[f].y;
                }
            } else {
                p1 = *(const float2*)&P[(size_t)(base + n)*PST + 128 + c0 + cc];
            }
            float2 t;
            t.x = p1.x + (sa.x + sb.x)*AGG_NORM;
            t.y = p1.y + (sa.y + sb.y)*AGG_NORM;
            *(float2*)&st[n*32 + cc] = t;
        }
    }
    __syncthreads();

    // ---- pass 2: h = lrelu(P0 + A*t + b), fused pool ----
    float2 biav = *(const float2*)&bias[c0 + cc];
    float2 pm = make_float2(0.f, 0.f);
    float2 px = make_float2(-1e30f, -1e30f);
    {
        float2 w0v[FIN];
        if (L1) {
#pragma unroll
            for (int f = 0; f < FIN; f++)
                w0v[f] = *(const float2*)&Wc[(0*FIN + f)*CC + c0 + cc];
        }
#pragma unroll
        for (int j = 0; j < 8; j++) {
            int n = w*16 + j*2 + sub;
            const uint16_t* nbp = nb16 + n*KNN;
            float2 sa = make_float2(0.f, 0.f), sb = make_float2(0.f, 0.f);
#pragma unroll
            for (int k = 0; k < 14; k += 2) {
                float2 va = *(const float2*)(stb + nbp[k]);
                float2 vb = *(const float2*)(stb + nbp[k+1]);
                sa.x += va.x; sa.y += va.y;
                sb.x += vb.x; sb.y += vb.y;
            }
            {
                float2 va = *(const float2*)(stb + nbp[14]);
                sa.x += va.x; sa.y += va.y;
            }
            float2 p0;
            if (L1) {
                p0 = make_float2(0.f, 0.f);
#pragma unroll
                for (int f = 0; f < FIN; f++) {
                    float xv = xs[n*8 + f];
                    p0.x += xv*w0v[f].x; p0.y += xv*w0v[f].y;
                }
            } else {
                p0 = *(const float2*)&P[(size_t)(base + n)*PST + c0 + cc];
            }
            float2 v;
            v.x = p0.x + (sa.x + sb.x)*AGG_NORM + biav.x;
            v.y = p0.y + (sa.y + sb.y)*AGG_NORM + biav.y;
            v.x = (v.x > 0.f) ? v.x : LEAKY*v.x;
            v.y = (v.y > 0.f) ? v.y : LEAKY*v.y;

            __nv_bfloat162 hh = make_bfloat162(__float2bfloat16(v.x), __float2bfloat16(v.y));
            *(uint32_t*)&hhi[(size_t)(base + n)*CC + c0 + cc] = *(uint32_t*)&hh;
            __nv_bfloat162 ll = make_bfloat162(
                __float2bfloat16(v.x - __bfloat162float(hh.x)),
                __float2bfloat16(v.y - __bfloat162float(hh.y)));
            *(uint32_t*)&hlo[(size_t)(base + n)*CC + c0 + cc] = *(uint32_t*)&ll;

            pm.x += v.x; pm.y += v.y;
            px.x = fmaxf(px.x, v.x); px.y = fmaxf(px.y, v.y);
        }
    }

    // ---- pool reduce: 32 (w,sub) groups x 32 channels ----
    __syncthreads();
    const int gidx = w*2 + sub;
    *(float2*)&s2[gidx*32 + cc] = pm;
    *(float2*)&st[gidx*32 + cc] = px;
    __syncthreads();
    if (tid < 32) {
        float m = 0.0f, xx = -1e30f;
#pragma unroll 8
        for (int gg = 0; gg < 32; gg++) {
            m  += s2[gg*32 + tid];
            xx  = fmaxf(xx, st[gg*32 + tid]);
        }
        g[gph*C2 + layer*256 + c0 + tid]       = m*(1.0f/MG);
        g[gph*C2 + layer*256 + 128 + c0 + tid] = xx;
    }
}

// ---------------- cp.async double-buffered mma.sync bf16-split GEMM (R9 config) ------
#define TP 72
#define ROWB (TP*2)
template<int BM, int BN, int WM, int WN>
__global__ void __launch_bounds__(WM*WN*32)
mma_gemm(const __nv_bfloat16* __restrict__ Ahi, const __nv_bfloat16* __restrict__ Alo, int lda,
         const __nv_bfloat16* __restrict__ Bhi, const __nv_bfloat16* __restrict__ Blo, int ldb,
         int K, float* __restrict__ Cf, int ldc, size_t zstride) {
    constexpr int THREADS = WM*WN*32;
    constexpr int MT = BM/WM/16;
    constexpr int NT = BN/WN/8;
    constexpr int OF_AL = BM*ROWB;
    constexpr int OF_BH = 2*BM*ROWB;
    constexpr int OF_BL = 2*BM*ROWB + BN*ROWB;
    constexpr int STAGE = (2*BM + 2*BN)*ROWB;
    extern __shared__ char smc[];
    const uint32_t sb = smem_u32(smc);
    const int tid = threadIdx.x, wid = tid >> 5, lane = tid & 31;
    const int bm = blockIdx.y*BM, bn = blockIdx.x*BN;
    const int kbase = blockIdx.z*K;
    const int wm = wid % WM, wn = wid / WM;

    float acc[MT][NT][4] = {};

    auto prefetch = [&](int kc, int stage) {
        uint32_t base = sb + stage*STAGE;
        int k0 = kbase + kc*64;
#pragma unroll
        for (int q = tid; q < BM*8; q += THREADS) {
            int r = q >> 3, c8 = q & 7;
            cpa16(base + r*ROWB + c8*16,          Ahi + (size_t)(bm + r)*lda + k0 + c8*8);
            cpa16(base + OF_AL + r*ROWB + c8*16,  Alo + (size_t)(bm + r)*lda + k0 + c8*8);
        }
#pragma unroll
        for (int q = tid; q < BN*8; q += THREADS) {
            int r = q >> 3, c8 = q & 7;
            cpa16(base + OF_BH + r*ROWB + c8*16,  Bhi + (size_t)(bn + r)*ldb + k0 + c8*8);
            cpa16(base + OF_BL + r*ROWB + c8*16,  Blo + (size_t)(bn + r)*ldb + k0 + c8*8);
        }
        cpa_commit();
    };

    const int ar = lane & 15, ac = (lane >> 4) << 3;
    const int l16 = lane & 15;
    const int br = l16 & 7, bc = (l16 >> 3) << 3;

    const int nk = K/64;
    prefetch(0, 0);
    for (int kc = 0; kc < nk; kc++) {
        if (kc + 1 < nk) { prefetch(kc + 1, (kc + 1) & 1); cpa_wait1(); }
        else             { cpa_wait0(); }
        __syncthreads();
        uint32_t base = sb + (kc & 1)*STAGE;
#pragma unroll
        for (int kk = 0; kk < 64; kk += 16) {
            uint32_t ah[MT][4], al[MT][4], bh[NT][2], bl[NT][2];
#pragma unroll
            for (int mt = 0; mt < MT; mt++) {
                uint32_t off = (wm*(BM/WM) + mt*16 + ar)*ROWB + (kk + ac)*2;
                ldm_x4(ah[mt], base + off);
                ldm_x4(al[mt], base + OF_AL + off);
            }
#pragma unroll
            for (int nt = 0; nt < NT; nt++) {
                uint32_t off = (wn*(BN/WN) + nt*8 + br)*ROWB + (kk + bc)*2;
                ldm_x2(bh[nt], base + OF_BH + off);
                ldm_x2(bl[nt], base + OF_BL + off);
            }
#pragma unroll
            for (int mt = 0; mt < MT; mt++)
#pragma unroll
                for (int nt = 0; nt < NT; nt++) {
                    mma16816(acc[mt][nt], ah[mt], bh[nt]);
                    mma16816(acc[mt][nt], ah[mt], bl[nt]);
                    mma16816(acc[mt][nt], al[mt], bh[nt]);
                }
        }
        __syncthreads();
    }

    float* Co = Cf + (size_t)blockIdx.z*zstride;
    const int er = lane >> 2, ec = (lane & 3)*2;
#pragma unroll
    for (int mt = 0; mt < MT; mt++) {
#pragma unroll
        for (int nt = 0; nt < NT; nt++) {
            int row0 = bm + wm*(BM/WM) + mt*16 + er;
            int col0 = bn + wn*(BN/WN) + nt*8 + ec;
#pragma unroll
            for (int half = 0; half < 2; half++) {
                int row = row0 + half*8;
                float2 v = make_float2(acc[mt][nt][half*2 + 0], acc[mt][nt][half*2 + 1]);
                *reinterpret_cast<float2*>(&Co[(size_t)row*ldc + col0]) = v;
            }
        }
    }
}
#define GEMM_SMEM_CONV (2*(2*128 + 2*128)*ROWB)
#define GEMM_SMEM_MLP  (2*(2*64 + 2*128)*ROWB)

// ---------------- MLP finalize --------------------------------------------------------
__global__ void mlp_fin(const float* __restrict__ part, const float* __restrict__ bias,
                        float* __restrict__ gf,
                        __nv_bfloat16* __restrict__ ohi, __nv_bfloat16* __restrict__ olo) {
    int idx = blockIdx.x*256 + threadIdx.x;
    float v = part[idx] + part[NBATCH*C2 + idx]
            + part[2*NBATCH*C2 + idx] + part[3*NBATCH*C2 + idx];
    v += bias[idx % C2];
    v = (v > 0.0f) ? v : LEAKY*v;
    __nv_bfloat16 h = __float2bfloat16(v);
    ohi[idx] = h;
    olo[idx] = __float2bfloat16(v - __bfloat162float(h));
    if (gf) gf[idx] = v;
}

// ---------------- batch-norm -> bf16 split -----------------------------------------
__global__ void bn_kernel(const float* __restrict__ g, const float* __restrict__ gamma,
                          const float* __restrict__ beta,
                          __nv_bfloat16* __restrict__ ohi, __nv_bfloat16* __restrict__ olo) {
    __shared__ float red[256];
    int c = blockIdx.x, t = threadIdx.x;
    float v = g[t*C2 + c];
    red[t] = v; __syncthreads();
    for (int s = 128; s > 0; s >>= 1) { if (t < s) red[t] += red[t+s]; __syncthreads(); }
    float mu = red[0]*(1.0f/NBATCH);
    __syncthreads();
    float d = v - mu;
    red[t] = d*d; __syncthreads();
    for (int s = 128; s > 0; s >>= 1) { if (t < s) red[t] += red[t+s]; __syncthreads(); }
    float var = red[0]*(1.0f/NBATCH);
    float sc = rsqrtf(var + 1e-5f)*gamma[c];
    float o = (v - mu)*sc + beta[c];
    __nv_bfloat16 oh = __float2bfloat16(o);
    ohi[t*C2 + c] = oh;
    olo[t*C2 + c] = __float2bfloat16(o - __bfloat162float(oh));
}

// ---------------- head: (256,768)@(768,3) + tanh on cols 0,1 ------------------------
__global__ void head_kernel(const float* __restrict__ g, const float* __restrict__ Wo,
                            const float* __restrict__ bo, float* __restrict__ y) {
    int b = blockIdx.x;
    int w = threadIdx.y, l = threadIdx.x;
    float s = 0.0f;
    for (int f = l; f < C2; f += 32) s += g[b*C2 + f]*Wo[f*3 + w];
#pragma unroll
    for (int o = 16; o; o >>= 1) s += __shfl_down_sync(0xffffffff, s, o);
    if (l == 0) {
        float v = s + bo[w];
        if (w < 2) v = tanhf(v);
        y[b*3 + w] = v;
    }
}

// ---------------- launch --------------------------------------------------------------
extern "C" void kernel_launch(void* const* d_in, const int* in_sizes, int n_in,
                              void* d_out, int out_size) {
    const float* x   = (const float*)d_in[0];
    const float* Wc1 = (const float*)d_in[1];  const float* bc1 = (const float*)d_in[2];
    const float* Wc2 = (const float*)d_in[3];  const float* bc2 = (const float*)d_in[4];
    const float* Wc3 = (const float*)d_in[5];  const float* bc3 = (const float*)d_in[6];
    const float* bng = (const float*)d_in[7];  const float* bnb = (const float*)d_in[8];
    const float* Wm[5]; const float* bmv[5];
    for (int i = 0; i < 5; i++) { Wm[i] = (const float*)d_in[9+2*i]; bmv[i] = (const float*)d_in[10+2*i]; }
    const float* Wo = (const float*)d_in[19];  const float* bo = (const float*)d_in[20];
    float* y = (float*)d_out;

    int* knn; float *P, *pool, *gf, *part;
    __nv_bfloat16 *hhi, *hlo, *ghiA, *gloA, *ghiB, *gloB, *WctHi, *WctLo, *WmtHi, *WmtLo;
    cudaGetSymbolAddress((void**)&knn,  g_knn);
    cudaGetSymbolAddress((void**)&P,    g_P);
    cudaGetSymbolAddress((void**)&pool, g_pool);
    cudaGetSymbolAddress((void**)&gf,   g_gf);
    cudaGetSymbolAddress((void**)&part, g_part);
    cudaGetSymbolAddress((void**)&hhi,  g_hhi);
    cudaGetSymbolAddress((void**)&hlo,  g_hlo);
    cudaGetSymbolAddress((void**)&ghiA, g_ghiA);  cudaGetSymbolAddress((void**)&gloA, g_gloA);
    cudaGetSymbolAddress((void**)&ghiB, g_ghiB);  cudaGetSymbolAddress((void**)&gloB, g_gloB);
    cudaGetSymbolAddress((void**)&WctHi, g_WctHi); cudaGetSymbolAddress((void**)&WctLo, g_WctLo);
    cudaGetSymbolAddress((void**)&WmtHi, g_WmtHi); cudaGetSymbolAddress((void**)&WmtLo, g_WmtLo);

    cudaFuncSetAttribute(tag_agg<true>,  cudaFuncAttributeMaxDynamicSharedMemorySize, AGG_SMEM_L1);
    cudaFuncSetAttribute(tag_agg<false>, cudaFuncAttributeMaxDynamicSharedMemorySize, AGG_SMEM_MAIN);
    cudaFuncSetAttribute((const void*)mma_gemm<128,128,2,4>,
                         cudaFuncAttributeMaxDynamicSharedMemorySize, GEMM_SMEM_CONV);
    cudaFuncSetAttribute((const void*)mma_gemm<64,128,2,4>,
                         cudaFuncAttributeMaxDynamicSharedMemorySize, GEMM_SMEM_MLP);

    // 0. weight prep
    Ptr2 wc{ {Wc2, Wc3} };
    wprep_conv_all<<<(2*3*CC*CC + 255)/256, 256>>>(wc, WctHi, WctLo);
    Ptr5 wmp{ {Wm[0], Wm[1], Wm[2], Wm[3], Wm[4]} };
    wprep_mlp_all<<<(5*C2*C2 + 255)/256, 256>>>(wmp, WmtHi, WmtLo);

    // 1. kNN (warp-per-node)
    knn_kernel<<<dim3(32, NBATCH), 256>>>(x, knn);

    // 2. layer 1 fused
    tag_agg<true><<<dim3(4, NBATCH), AGG_THREADS, AGG_SMEM_L1>>>(
        nullptr, x, Wc1, knn, bc1, hhi, hlo, pool, 0);

    // 3. layer 2
    mma_gemm<128,128,2,4><<<dim3(3, NTOT/128, 1), 256, GEMM_SMEM_CONV>>>(
        hhi, hlo, CC, WctHi, WctLo, CC, CC, P, PST, 0);
    tag_agg<false><<<dim3(4, NBATCH), AGG_THREADS, AGG_SMEM_MAIN>>>(
        P, nullptr, nullptr, knn, bc2, hhi, hlo, pool, 1);

    // 4. layer 3
    mma_gemm<128,128,2,4><<<dim3(3, NTOT/128, 1), 256, GEMM_SMEM_CONV>>>(
        hhi, hlo, CC, WctHi + 3*CC*CC, WctLo + 3*CC*CC, CC, CC, P, PST, 0);
    tag_agg<false><<<dim3(4, NBATCH), AGG_THREADS, AGG_SMEM_MAIN>>>(
        P, nullptr, nullptr, knn, bc3, hhi, hlo, pool, 2);

    // 5. batch-norm -> bf16 split
    bn_kernel<<<C2, 256>>>(pool, bng, bnb, ghiA, gloA);

    // 6. MLP x5: split-K x4 GEMM + finalize
    __nv_bfloat16 *chi = ghiA, *clo = gloA, *nhi = ghiB, *nlo = gloB;
    for (int i = 0; i < 5; i++) {
        mma_gemm<64,128,2,4><<<dim3(C2/128, NBATCH/64, 4), 256, GEMM_SMEM_MLP>>>(
            chi, clo, C2, WmtHi + (size_t)i*C2*C2, WmtLo + (size_t)i*C2*C2, C2,
            C2/4, part, C2, (size_t)NBATCH*C2);
        mlp_fin<<<NBATCH*C2/256, 256>>>(part, bmv[i], (i == 4) ? gf : nullptr, nhi, nlo);
        __nv_bfloat16* t1 = chi; chi = nhi; nhi = t1;
        __nv_bfloat16* t2 = clo; clo = nlo; nlo = t2;
    }

    // 7. head + fused tanh
    head_kernel<<<NBATCH, dim3(32, 3)>>>(gf, Wo, bo, y);
}

// round 14
// speedup vs baseline: 1.5923x; 1.5923x over previous
#include <cuda_runtime.h>
#include <cuda_bf16.h>
#include <cstdint>
#include <math.h>

#define NBATCH 256
#define MG     256
#define NTOT   (NBATCH*MG)      // 65536 nodes
#define KNN    15
#define FIN    7
#define CC     128
#define PST    384
#define C2     768
#define LEAKY  0.01f
#define AGG_NORM (1.0f/15.0f)

// ---------------- scratch ------------------------------------------------------
__device__ int   g_knn[NTOT*KNN];
__device__ float g_P[(size_t)NTOT*PST];
__device__ __nv_bfloat16 g_hhi[(size_t)NTOT*CC];
__device__ __nv_bfloat16 g_hlo[(size_t)NTOT*CC];
__device__ float g_pool[NBATCH*C2];
__device__ float g_gf[NBATCH*C2];
__device__ float g_part[4*NBATCH*C2];
__device__ __nv_bfloat16 g_ghiA[NBATCH*C2], g_gloA[NBATCH*C2];
__device__ __nv_bfloat16 g_ghiB[NBATCH*C2], g_gloB[NBATCH*C2];
__device__ __nv_bfloat16 g_WctHi[2*3*CC*CC], g_WctLo[2*3*CC*CC];
__device__ __nv_bfloat16 g_WmtHi[5*C2*C2],   g_WmtLo[5*C2*C2];

// ---------------- helpers -------------------------------------------------------
__device__ __forceinline__ uint32_t smem_u32(const void* p) {
    uint32_t a;
    asm("{ .reg .u64 t; cvta.to.shared.u64 t, %1; cvt.u32.u64 %0, t; }" : "=r"(a) : "l"(p));
    return a;
}
__device__ __forceinline__ void ldm_x4(uint32_t* r, uint32_t addr) {
    asm volatile("ldmatrix.sync.aligned.m8n8.x4.shared.b16 {%0,%1,%2,%3}, [%4];"
                 : "=r"(r[0]), "=r"(r[1]), "=r"(r[2]), "=r"(r[3]) : "r"(addr));
}
__device__ __forceinline__ void ldm_x2(uint32_t* r, uint32_t addr) {
    asm volatile("ldmatrix.sync.aligned.m8n8.x2.shared.b16 {%0,%1}, [%2];"
                 : "=r"(r[0]), "=r"(r[1]) : "r"(addr));
}
__device__ __forceinline__ void mma16816(float* c, const uint32_t* a, const uint32_t* b) {
    asm volatile("mma.sync.aligned.m16n8k16.row.col.f32.bf16.bf16.f32 "
        "{%0,%1,%2,%3}, {%4,%5,%6,%7}, {%8,%9}, {%0,%1,%2,%3};"
        : "+f"(c[0]), "+f"(c[1]), "+f"(c[2]), "+f"(c[3])
        : "r"(a[0]), "r"(a[1]), "r"(a[2]), "r"(a[3]), "r"(b[0]), "r"(b[1]));
}
__device__ __forceinline__ void cpa16(uint32_t dst, const void* src) {
    asm volatile("cp.async.ca.shared.global [%0], [%1], 16;" :: "r"(dst), "l"(src));
}
__device__ __forceinline__ void cpa_commit() { asm volatile("cp.async.commit_group;"); }
__device__ __forceinline__ void cpa_wait1()  { asm volatile("cp.async.wait_group 1;"); }
__device__ __forceinline__ void cpa_wait0()  { asm volatile("cp.async.wait_group 0;"); }

// ---------------- kNN: warp per node, warp-argmin top-15 (R12) ----------------------
__global__ void __launch_bounds__(256)
knn_kernel(const float* __restrict__ x, int* __restrict__ knn) {
    __shared__ float4 pos[MG];
    __shared__ float  sq[MG];
    const int g    = blockIdx.y;
    const int nb   = blockIdx.x;
    const int tid  = threadIdx.x;
    const int w    = tid >> 5;
    const int lane = tid & 31;

    {
        const float* xr = x + (size_t)(g*MG + tid)*FIN;
        float4 p = make_float4(xr[0], xr[1], xr[2], xr[3]);
        pos[tid] = p;
        sq[tid]  = p.x*p.x + p.y*p.y + p.z*p.z + p.w*p.w;
    }
    __syncthreads();

    const int n = nb*8 + w;
    const float4 p = pos[n];
    const float mysq = sq[n];
    const int jbase = lane*8;
    float d[8];
#pragma unroll
    for (int i = 0; i < 8; i++) {
        int j = jbase + i;
        float4 q = pos[j];
        float dd = mysq + sq[j] - 2.0f*(p.x*q.x + p.y*q.y + p.z*q.z + p.w*q.w);
        d[i] = (j == n) ? 1e30f : dd;
    }

    int* out = knn + (size_t)(g*MG + n)*KNN;
#pragma unroll 1
    for (int it = 0; it < KNN; it++) {
        float bv = d[0]; int bi = 0;
#pragma unroll
        for (int i = 1; i < 8; i++) if (d[i] < bv) { bv = d[i]; bi = i; }
        float v = bv; int j = jbase + bi;
#pragma unroll
        for (int o = 16; o; o >>= 1) {
            float v2 = __shfl_xor_sync(0xffffffff, v, o);
            int   j2 = __shfl_xor_sync(0xffffffff, j, o);
            if (v2 < v || (v2 == v && j2 < j)) { v = v2; j = j2; }
        }
        if (lane == (j >> 3)) {
            int slot = j & 7;
#pragma unroll
            for (int i = 0; i < 8; i++) if (i == slot) d[i] = 1e30f;
        }
        if (lane == 0) out[it] = g*MG + j;
    }
}

// ---------------- weight prep (single merged kernel) --------------------------------
struct Ptr7 { const float* p[7]; };   // [Wc2, Wc3, Wm0..Wm4]
#define WCONV_ELEMS (3*CC*CC)         // 49152 per conv layer
#define WMLP_ELEMS  (C2*C2)           // 589824 per mlp layer
#define WPREP_TOTAL (2*WCONV_ELEMS + 5*WMLP_ELEMS)
__global__ void wprep_all(Ptr7 Ws,
                          __nv_bfloat16* __restrict__ chi, __nv_bfloat16* __restrict__ clo,
                          __nv_bfloat16* __restrict__ mhi, __nv_bfloat16* __restrict__ mlo) {
    int idx = blockIdx.x*256 + threadIdx.x;
    if (idx >= WPREP_TOTAL) return;
    if (idx < 2*WCONV_ELEMS) {
        int l = idx / WCONV_ELEMS, r0 = idx % WCONV_ELEMS;
        int s = r0 / (CC*CC), r = r0 % (CC*CC), n = r / CC, k = r % CC;
        float v = Ws.p[l][(s*CC + k)*CC + n];
        __nv_bfloat16 h = __float2bfloat16(v);
        chi[idx] = h; clo[idx] = __float2bfloat16(v - __bfloat162float(h));
    } else {
        int q = idx - 2*WCONV_ELEMS;
        int i = q / WMLP_ELEMS, r = q % WMLP_ELEMS, n = r / C2, k = r % C2;
        float v = Ws.p[2 + i][k*C2 + n];
        __nv_bfloat16 h = __float2bfloat16(v);
        mhi[q] = h; mlo[q] = __float2bfloat16(v - __bfloat162float(h));
    }
}

// ---------------- fused TAGConv aggregate + activate + pool (R12 scalar) ------------
#define AGG_THREADS 512
template<bool L1>
__global__ void __launch_bounds__(AGG_THREADS)
tag_agg(const float* __restrict__ P, const float* __restrict__ x,
        const float* __restrict__ Wc, const int* __restrict__ knn,
        const float* __restrict__ bias,
        __nv_bfloat16* __restrict__ hhi, __nv_bfloat16* __restrict__ hlo,
        float* __restrict__ g, int layer) {
    extern __shared__ float sm[];
    float*   s2  = sm;
    float*   st  = sm + 8192;
    uint8_t* nbs = (uint8_t*)(sm + 16384);
    float*   xs  = (float*)(nbs + 3840);

    const int c0   = blockIdx.x*32;
    const int gph  = blockIdx.y;
    const int base = gph*MG;
    const int tid  = threadIdx.x;
    const int c    = tid & 31;
    const int ng   = tid >> 5;

    for (int i = tid; i < MG*KNN; i += AGG_THREADS)
        nbs[i] = (uint8_t)(knn[(size_t)base*KNN + i] & (MG-1));

    float w0[FIN], w1[FIN], w2[FIN];
    if (L1) {
#pragma unroll
        for (int f = 0; f < FIN; f++) {
            w0[f] = Wc[(0*FIN + f)*CC + c0 + c];
            w1[f] = Wc[(1*FIN + f)*CC + c0 + c];
            w2[f] = Wc[(2*FIN + f)*CC + c0 + c];
        }
        for (int i = tid; i < MG*FIN; i += AGG_THREADS)
            xs[(i/FIN)*8 + (i%FIN)] = x[(size_t)base*FIN + i];
    }

    if (L1) {
        __syncthreads();
#pragma unroll
        for (int j = 0; j < 16; j++) {
            int n = ng*16 + j;
            float acc = 0.0f;
#pragma unroll
            for (int f = 0; f < FIN; f++) acc += xs[n*8 + f]*w2[f];
            s2[n*32 + c] = acc;
        }
    } else {
#pragma unroll
        for (int j = 0; j < 16; j++) {
            int n = ng*16 + j;
            s2[n*32 + c] = P[(size_t)(base + n)*PST + 256 + c0 + c];
        }
    }
    __syncthreads();

#pragma unroll
    for (int j = 0; j < 16; j++) {
        int n = ng*16 + j;
        const uint8_t* nbp = nbs + n*KNN;
        float sa = 0.0f, sb = 0.0f;
#pragma unroll
        for (int k = 0; k < 14; k += 2) {
            sa += s2[(int)nbp[k]*32 + c];
            sb += s2[(int)nbp[k+1]*32 + c];
        }
        sa += s2[(int)nbp[14]*32 + c];
        float p1;
        if (L1) {
            p1 = 0.0f;
#pragma unroll
            for (int f = 0; f < FIN; f++) p1 += xs[n*8 + f]*w1[f];
        } else {
            p1 = P[(size_t)(base + n)*PST + 128 + c0 + c];
        }
        st[n*32 + c] = p1 + (sa + sb)*AGG_NORM;
    }
    __syncthreads();

    float bia = bias[c0 + c];
    float pm = 0.0f, px = -1e30f;
#pragma unroll
    for (int j = 0; j < 16; j++) {
        int n = ng*16 + j;
        const uint8_t* nbp = nbs + n*KNN;
        float sa = 0.0f, sb = 0.0f;
#pragma unroll
        for (int k = 0; k < 14; k += 2) {
            sa += st[(int)nbp[k]*32 + c];
            sb += st[(int)nbp[k+1]*32 + c];
        }
        sa += st[(int)nbp[14]*32 + c];
        float p0;
        if (L1) {
            p0 = 0.0f;
#pragma unroll
            for (int f = 0; f < FIN; f++) p0 += xs[n*8 + f]*w0[f];
        } else {
            p0 = P[(size_t)(base + n)*PST + c0 + c];
        }
        float v = p0 + (sa + sb)*AGG_NORM + bia;
        v = (v > 0.0f) ? v : LEAKY*v;
        __nv_bfloat16 vh = __float2bfloat16(v);
        hhi[(size_t)(base + n)*CC + c0 + c] = vh;
        hlo[(size_t)(base + n)*CC + c0 + c] = __float2bfloat16(v - __bfloat162float(vh));
        pm += v; px = fmaxf(px, v);
    }

    s2[ng*32 + c]        = pm;
    s2[1024 + ng*32 + c] = px;
    __syncthreads();
    if (ng == 0) {
        float m = 0.0f, xx = -1e30f;
#pragma unroll
        for (int q = 0; q < 16; q++) {
            m += s2[q*32 + c];
            xx = fmaxf(xx, s2[1024 + q*32 + c]);
        }
        g[gph*C2 + layer*256 + c0 + c]       = m*(1.0f/MG);
        g[gph*C2 + layer*256 + 128 + c0 + c] = xx;
    }
}
#define AGG_SMEM_MAIN (16384*4 + 3840)
#define AGG_SMEM_L1   (AGG_SMEM_MAIN + 2048*4)

// ---------------- cp.async double-buffered mma.sync bf16-split GEMM (R9/R12 config) --
#define TP 72
#define ROWB (TP*2)
template<int BM, int BN, int WM, int WN>
__global__ void __launch_bounds__(WM*WN*32)
mma_gemm(const __nv_bfloat16* __restrict__ Ahi, const __nv_bfloat16* __restrict__ Alo, int lda,
         const __nv_bfloat16* __restrict__ Bhi, const __nv_bfloat16* __restrict__ Blo, int ldb,
         int K, float* __restrict__ Cf, int ldc, size_t zstride) {
    constexpr int THREADS = WM*WN*32;
    constexpr int MT = BM/WM/16;
    constexpr int NT = BN/WN/8;
    constexpr int OF_AL = BM*ROWB;
    constexpr int OF_BH = 2*BM*ROWB;
    constexpr int OF_BL = 2*BM*ROWB + BN*ROWB;
    constexpr int STAGE = (2*BM + 2*BN)*ROWB;
    extern __shared__ char smc[];
    const uint32_t sb = smem_u32(smc);
    const int tid = threadIdx.x, wid = tid >> 5, lane = tid & 31;
    const int bm = blockIdx.y*BM, bn = blockIdx.x*BN;
    const int kbase = blockIdx.z*K;
    const int wm = wid % WM, wn = wid / WM;

    float acc[MT][NT][4] = {};

    auto prefetch = [&](int kc, int stage) {
        uint32_t base = sb + stage*STAGE;
        int k0 = kbase + kc*64;
#pragma unroll
        for (int q = tid; q < BM*8; q += THREADS) {
            int r = q >> 3, c8 = q & 7;
            cpa16(base + r*ROWB + c8*16,          Ahi + (size_t)(bm + r)*lda + k0 + c8*8);
            cpa16(base + OF_AL + r*ROWB + c8*16,  Alo + (size_t)(bm + r)*lda + k0 + c8*8);
        }
#pragma unroll
        for (int q = tid; q < BN*8; q += THREADS) {
            int r = q >> 3, c8 = q & 7;
            cpa16(base + OF_BH + r*ROWB + c8*16,  Bhi + (size_t)(bn + r)*ldb + k0 + c8*8);
            cpa16(base + OF_BL + r*ROWB + c8*16,  Blo + (size_t)(bn + r)*ldb + k0 + c8*8);
        }
        cpa_commit();
    };

    const int ar = lane & 15, ac = (lane >> 4) << 3;
    const int l16 = lane & 15;
    const int br = l16 & 7, bc = (l16 >> 3) << 3;

    const int nk = K/64;
    prefetch(0, 0);
    for (int kc = 0; kc < nk; kc++) {
        if (kc + 1 < nk) { prefetch(kc + 1, (kc + 1) & 1); cpa_wait1(); }
        else             { cpa_wait0(); }
        __syncthreads();
        uint32_t base = sb + (kc & 1)*STAGE;
#pragma unroll
        for (int kk = 0; kk < 64; kk += 16) {
            uint32_t ah[MT][4], al[MT][4], bh[NT][2], bl[NT][2];
#pragma unroll
            for (int mt = 0; mt < MT; mt++) {
                uint32_t off = (wm*(BM/WM) + mt*16 + ar)*ROWB + (kk + ac)*2;
                ldm_x4(ah[mt], base + off);
                ldm_x4(al[mt], base + OF_AL + off);
            }
#pragma unroll
            for (int nt = 0; nt < NT; nt++) {
                uint32_t off = (wn*(BN/WN) + nt*8 + br)*ROWB + (kk + bc)*2;
                ldm_x2(bh[nt], base + OF_BH + off);
                ldm_x2(bl[nt], base + OF_BL + off);
            }
#pragma unroll
            for (int mt = 0; mt < MT; mt++)
#pragma unroll
                for (int nt = 0; nt < NT; nt++) {
                    mma16816(acc[mt][nt], ah[mt], bh[nt]);
                    mma16816(acc[mt][nt], ah[mt], bl[nt]);
                    mma16816(acc[mt][nt], al[mt], bh[nt]);
                }
        }
        __syncthreads();
    }

    float* Co = Cf + (size_t)blockIdx.z*zstride;
    const int er = lane >> 2, ec = (lane & 3)*2;
#pragma unroll
    for (int mt = 0; mt < MT; mt++) {
#pragma unroll
        for (int nt = 0; nt < NT; nt++) {
            int row0 = bm + wm*(BM/WM) + mt*16 + er;
            int col0 = bn + wn*(BN/WN) + nt*8 + ec;
#pragma unroll
            for (int half = 0; half < 2; half++) {
                int row = row0 + half*8;
                float2 v = make_float2(acc[mt][nt][half*2 + 0], acc[mt][nt][half*2 + 1]);
                *reinterpret_cast<float2*>(&Co[(size_t)row*ldc + col0]) = v;
            }
        }
    }
}
#define GEMM_SMEM_CONV (2*(2*128 + 2*128)*ROWB)
#define GEMM_SMEM_MLP  (2*(2*64 + 2*128)*ROWB)

// ---------------- MLP finalize (float4 vectorized) ------------------------------------
__global__ void mlp_fin(const float4* __restrict__ part, const float* __restrict__ bias,
                        float4* __restrict__ gf,
                        uint2* __restrict__ ohi, uint2* __restrict__ olo) {
    int idx = blockIdx.x*256 + threadIdx.x;          // NBATCH*C2/4 = 49152
    const int Q = NBATCH*C2/4;
    float4 a = part[idx], b = part[Q + idx], cpp = part[2*Q + idx], dd = part[3*Q + idx];
    int cb = (idx*4) % C2;
    float4 bi = *(const float4*)&bias[cb];
    float4 v;
    v.x = a.x + b.x + cpp.x + dd.x + bi.x;
    v.y = a.y + b.y + cpp.y + dd.y + bi.y;
    v.z = a.z + b.z + cpp.z + dd.z + bi.z;
    v.w = a.w + b.w + cpp.w + dd.w + bi.w;
    v.x = (v.x > 0.f) ? v.x : LEAKY*v.x;
    v.y = (v.y > 0.f) ? v.y : LEAKY*v.y;
    v.z = (v.z > 0.f) ? v.z : LEAKY*v.z;
    v.w = (v.w > 0.f) ? v.w : LEAKY*v.w;
    __nv_bfloat162 h01 = make_bfloat162(__float2bfloat16(v.x), __float2bfloat16(v.y));
    __nv_bfloat162 h23 = make_bfloat162(__float2bfloat16(v.z), __float2bfloat16(v.w));
    ohi[idx] = make_uint2(*(uint32_t*)&h01, *(uint32_t*)&h23);
    __nv_bfloat162 l01 = make_bfloat162(__float2bfloat16(v.x - __bfloat162float(h01.x)),
                                        __float2bfloat16(v.y - __bfloat162float(h01.y)));
    __nv_bfloat162 l23 = make_bfloat162(__float2bfloat16(v.z - __bfloat162float(h23.x)),
                                        __float2bfloat16(v.w - __bfloat162float(h23.y)));
    olo[idx] = make_uint2(*(uint32_t*)&l01, *(uint32_t*)&l23);
    if (gf) gf[idx] = v;
}

// ---------------- batch-norm -> bf16 split -----------------------------------------
__global__ void bn_kernel(const float* __restrict__ g, const float* __restrict__ gamma,
                          const float* __restrict__ beta,
                          __nv_bfloat16* __restrict__ ohi, __nv_bfloat16* __restrict__ olo) {
    __shared__ float red[256];
    int c = blockIdx.x, t = threadIdx.x;
    float v = g[t*C2 + c];
    red[t] = v; __syncthreads();
    for (int s = 128; s > 0; s >>= 1) { if (t < s) red[t] += red[t+s]; __syncthreads(); }
    float mu = red[0]*(1.0f/NBATCH);
    __syncthreads();
    float d = v - mu;
    red[t] = d*d; __syncthreads();
    for (int s = 128; s > 0; s >>= 1) { if (t < s) red[t] += red[t+s]; __syncthreads(); }
    float var = red[0]*(1.0f/NBATCH);
    float sc = rsqrtf(var + 1e-5f)*gamma[c];
    float o = (v - mu)*sc + beta[c];
    __nv_bfloat16 oh = __float2bfloat16(o);
    ohi[t*C2 + c] = oh;
    olo[t*C2 + c] = __float2bfloat16(o - __bfloat162float(oh));
}

// ---------------- head: (256,768)@(768,3) + tanh on cols 0,1 ------------------------
__global__ void head_kernel(const float* __restrict__ g, const float* __restrict__ Wo,
                            const float* __restrict__ bo, float* __restrict__ y) {
    int b = blockIdx.x;
    int w = threadIdx.y, l = threadIdx.x;
    float s = 0.0f;
    for (int f = l; f < C2; f += 32) s += g[b*C2 + f]*Wo[f*3 + w];
#pragma unroll
    for (int o = 16; o; o >>= 1) s += __shfl_down_sync(0xffffffff, s, o);
    if (l == 0) {
        float v = s + bo[w];
        if (w < 2) v = tanhf(v);
        y[b*3 + w] = v;
    }
}

// ---------------- launch --------------------------------------------------------------
extern "C" void kernel_launch(void* const* d_in, const int* in_sizes, int n_in,
                              void* d_out, int out_size) {
    const float* x   = (const float*)d_in[0];
    const float* Wc1 = (const float*)d_in[1];  const float* bc1 = (const float*)d_in[2];
    const float* Wc2 = (const float*)d_in[3];  const float* bc2 = (const float*)d_in[4];
    const float* Wc3 = (const float*)d_in[5];  const float* bc3 = (const float*)d_in[6];
    const float* bng = (const float*)d_in[7];  const float* bnb = (const float*)d_in[8];
    const float* Wm[5]; const float* bmv[5];
    for (int i = 0; i < 5; i++) { Wm[i] = (const float*)d_in[9+2*i]; bmv[i] = (const float*)d_in[10+2*i]; }
    const float* Wo = (const float*)d_in[19];  const float* bo = (const float*)d_in[20];
    float* y = (float*)d_out;

    int* knn; float *P, *pool, *gf, *part;
    __nv_bfloat16 *hhi, *hlo, *ghiA, *gloA, *ghiB, *gloB, *WctHi, *WctLo, *WmtHi, *WmtLo;
    cudaGetSymbolAddress((void**)&knn,  g_knn);
    cudaGetSymbolAddress((void**)&P,    g_P);
    cudaGetSymbolAddress((void**)&pool, g_pool);
    cudaGetSymbolAddress((void**)&gf,   g_gf);
    cudaGetSymbolAddress((void**)&part, g_part);
    cudaGetSymbolAddress((void**)&hhi,  g_hhi);
    cudaGetSymbolAddress((void**)&hlo,  g_hlo);
    cudaGetSymbolAddress((void**)&ghiA, g_ghiA);  cudaGetSymbolAddress((void**)&gloA, g_gloA);
    cudaGetSymbolAddress((void**)&ghiB, g_ghiB);  cudaGetSymbolAddress((void**)&gloB, g_gloB);
    cudaGetSymbolAddress((void**)&WctHi, g_WctHi); cudaGetSymbolAddress((void**)&WctLo, g_WctLo);
    cudaGetSymbolAddress((void**)&WmtHi, g_WmtHi); cudaGetSymbolAddress((void**)&WmtLo, g_WmtLo);

    cudaFuncSetAttribute(tag_agg<true>,  cudaFuncAttributeMaxDynamicSharedMemorySize, AGG_SMEM_L1);
    cudaFuncSetAttribute(tag_agg<false>, cudaFuncAttributeMaxDynamicSharedMemorySize, AGG_SMEM_MAIN);
    cudaFuncSetAttribute((const void*)mma_gemm<128,128,2,4>,
                         cudaFuncAttributeMaxDynamicSharedMemorySize, GEMM_SMEM_CONV);
    cudaFuncSetAttribute((const void*)mma_gemm<64,128,2,4>,
                         cudaFuncAttributeMaxDynamicSharedMemorySize, GEMM_SMEM_MLP);

    // 0. weight prep (single merged kernel)
    Ptr7 wall{ {Wc2, Wc3, Wm[0], Wm[1], Wm[2], Wm[3], Wm[4]} };
    wprep_all<<<(WPREP_TOTAL + 255)/256, 256>>>(wall, WctHi, WctLo, WmtHi, WmtLo);

    // 1. kNN (warp-per-node)
    knn_kernel<<<dim3(32, NBATCH), 256>>>(x, knn);

    // 2. layer 1 fused
    tag_agg<true><<<dim3(4, NBATCH), AGG_THREADS, AGG_SMEM_L1>>>(
        nullptr, x, Wc1, knn, bc1, hhi, hlo, pool, 0);

    // 3. layer 2
    mma_gemm<128,128,2,4><<<dim3(3, NTOT/128, 1), 256, GEMM_SMEM_CONV>>>(
        hhi, hlo, CC, WctHi, WctLo, CC, CC, P, PST, 0);
    tag_agg<false><<<dim3(4, NBATCH), AGG_THREADS, AGG_SMEM_MAIN>>>(
        P, nullptr, nullptr, knn, bc2, hhi, hlo, pool, 1);

    // 4. layer 3
    mma_gemm<128,128,2,4><<<dim3(3, NTOT/128, 1), 256, GEMM_SMEM_CONV>>>(
        hhi, hlo, CC, WctHi + 3*CC*CC, WctLo + 3*CC*CC, CC, CC, P, PST, 0);
    tag_agg<false><<<dim3(4, NBATCH), AGG_THREADS, AGG_SMEM_MAIN>>>(
        P, nullptr, nullptr, knn, bc3, hhi, hlo, pool, 2);

    // 5. batch-norm -> bf16 split
    bn_kernel<<<C2, 256>>>(pool, bng, bnb, ghiA, gloA);

    // 6. MLP x5: split-K x4 GEMM + finalize
    __nv_bfloat16 *chi = ghiA, *clo = gloA, *nhi = ghiB, *nlo = gloB;
    for (int i = 0; i < 5; i++) {
        mma_gemm<64,128,2,4><<<dim3(C2/128, NBATCH/64, 4), 256, GEMM_SMEM_MLP>>>(
            chi, clo, C2, WmtHi + (size_t)i*C2*C2, WmtLo + (size_t)i*C2*C2, C2,
            C2/4, part, C2, (size_t)NBATCH*C2);
        mlp_fin<<<NBATCH*C2/4/256, 256>>>((const float4*)part, bmv[i],
            (i == 4) ? (float4*)gf : nullptr, (uint2*)nhi, (uint2*)nlo);
        __nv_bfloat16* t1 = chi; chi = nhi; nhi = t1;
        __nv_bfloat16* t2 = clo; clo = nlo; nlo = t2;
    }

    // 7. head + fused tanh
    head_kernel<<<NBATCH, dim3(32, 3)>>>(gf, Wo, bo, y);
}

// round 16
// speedup vs baseline: 1.6031x; 1.0068x over previous
#include <cuda_runtime.h>
#include <cuda_bf16.h>
#include <cstdint>
#include <math.h>

#define NBATCH 256
#define MG     256
#define NTOT   (NBATCH*MG)      // 65536 nodes
#define KNN    15
#define FIN    7
#define CC     128
#define PST    384
#define C2     768
#define LEAKY  0.01f
#define AGG_NORM (1.0f/15.0f)

// ---------------- scratch ------------------------------------------------------
__device__ int   g_knn[NTOT*KNN];
__device__ float g_P[(size_t)NTOT*PST];
__device__ __nv_bfloat16 g_hhi[(size_t)NTOT*CC];
__device__ __nv_bfloat16 g_hlo[(size_t)NTOT*CC];
__device__ float g_pool[NBATCH*C2];
__device__ float g_gf[NBATCH*C2];
__device__ float g_part[4*NBATCH*C2];
__device__ __nv_bfloat16 g_ghiA[NBATCH*C2], g_gloA[NBATCH*C2];
__device__ __nv_bfloat16 g_ghiB[NBATCH*C2], g_gloB[NBATCH*C2];
__device__ __nv_bfloat16 g_WctHi[2*3*CC*CC], g_WctLo[2*3*CC*CC];
__device__ __nv_bfloat16 g_WmtHi[5*C2*C2],   g_WmtLo[5*C2*C2];

// ---------------- helpers -------------------------------------------------------
__device__ __forceinline__ uint32_t smem_u32(const void* p) {
    uint32_t a;
    asm("{ .reg .u64 t; cvta.to.shared.u64 t, %1; cvt.u32.u64 %0, t; }" : "=r"(a) : "l"(p));
    return a;
}
__device__ __forceinline__ void ldm_x4(uint32_t* r, uint32_t addr) {
    asm volatile("ldmatrix.sync.aligned.m8n8.x4.shared.b16 {%0,%1,%2,%3}, [%4];"
                 : "=r"(r[0]), "=r"(r[1]), "=r"(r[2]), "=r"(r[3]) : "r"(addr));
}
__device__ __forceinline__ void ldm_x2(uint32_t* r, uint32_t addr) {
    asm volatile("ldmatrix.sync.aligned.m8n8.x2.shared.b16 {%0,%1}, [%2];"
                 : "=r"(r[0]), "=r"(r[1]) : "r"(addr));
}
__device__ __forceinline__ void mma16816(float* c, const uint32_t* a, const uint32_t* b) {
    asm volatile("mma.sync.aligned.m16n8k16.row.col.f32.bf16.bf16.f32 "
        "{%0,%1,%2,%3}, {%4,%5,%6,%7}, {%8,%9}, {%0,%1,%2,%3};"
        : "+f"(c[0]), "+f"(c[1]), "+f"(c[2]), "+f"(c[3])
        : "r"(a[0]), "r"(a[1]), "r"(a[2]), "r"(a[3]), "r"(b[0]), "r"(b[1]));
}
__device__ __forceinline__ void cpa16(uint32_t dst, const void* src) {
    asm volatile("cp.async.ca.shared.global [%0], [%1], 16;" :: "r"(dst), "l"(src));
}
__device__ __forceinline__ void cpa_commit() { asm volatile("cp.async.commit_group;"); }
__device__ __forceinline__ void cpa_wait1()  { asm volatile("cp.async.wait_group 1;"); }
__device__ __forceinline__ void cpa_wait0()  { asm volatile("cp.async.wait_group 0;"); }

// ---------------- kNN: warp per node, warp-argmin top-15 (R12) ----------------------
__global__ void __launch_bounds__(256)
knn_kernel(const float* __restrict__ x, int* __restrict__ knn) {
    __shared__ float4 pos[MG];
    __shared__ float  sq[MG];
    const int g    = blockIdx.y;
    const int nb   = blockIdx.x;
    const int tid  = threadIdx.x;
    const int w    = tid >> 5;
    const int lane = tid & 31;

    {
        const float* xr = x + (size_t)(g*MG + tid)*FIN;
        float4 p = make_float4(xr[0], xr[1], xr[2], xr[3]);
        pos[tid] = p;
        sq[tid]  = p.x*p.x + p.y*p.y + p.z*p.z + p.w*p.w;
    }
    __syncthreads();

    const int n = nb*8 + w;
    const float4 p = pos[n];
    const float mysq = sq[n];
    const int jbase = lane*8;
    float d[8];
#pragma unroll
    for (int i = 0; i < 8; i++) {
        int j = jbase + i;
        float4 q = pos[j];
        float dd = mysq + sq[j] - 2.0f*(p.x*q.x + p.y*q.y + p.z*q.z + p.w*q.w);
        d[i] = (j == n) ? 1e30f : dd;
    }

    int* out = knn + (size_t)(g*MG + n)*KNN;
#pragma unroll 1
    for (int it = 0; it < KNN; it++) {
        float bv = d[0]; int bi = 0;
#pragma unroll
        for (int i = 1; i < 8; i++) if (d[i] < bv) { bv = d[i]; bi = i; }
        float v = bv; int j = jbase + bi;
#pragma unroll
        for (int o = 16; o; o >>= 1) {
            float v2 = __shfl_xor_sync(0xffffffff, v, o);
            int   j2 = __shfl_xor_sync(0xffffffff, j, o);
            if (v2 < v || (v2 == v && j2 < j)) { v = v2; j = j2; }
        }
        if (lane == (j >> 3)) {
            int slot = j & 7;
#pragma unroll
            for (int i = 0; i < 8; i++) if (i == slot) d[i] = 1e30f;
        }
        if (lane == 0) out[it] = g*MG + j;
    }
}

// ---------------- weight prep (single merged kernel) --------------------------------
struct Ptr7 { const float* p[7]; };   // [Wc2, Wc3, Wm0..Wm4]
#define WCONV_ELEMS (3*CC*CC)
#define WMLP_ELEMS  (C2*C2)
#define WPREP_TOTAL (2*WCONV_ELEMS + 5*WMLP_ELEMS)
__global__ void wprep_all(Ptr7 Ws,
                          __nv_bfloat16* __restrict__ chi, __nv_bfloat16* __restrict__ clo,
                          __nv_bfloat16* __restrict__ mhi, __nv_bfloat16* __restrict__ mlo) {
    int idx = blockIdx.x*256 + threadIdx.x;
    if (idx >= WPREP_TOTAL) return;
    if (idx < 2*WCONV_ELEMS) {
        int l = idx / WCONV_ELEMS, r0 = idx % WCONV_ELEMS;
        int s = r0 / (CC*CC), r = r0 % (CC*CC), n = r / CC, k = r % CC;
        float v = Ws.p[l][(s*CC + k)*CC + n];
        __nv_bfloat16 h = __float2bfloat16(v);
        chi[idx] = h; clo[idx] = __float2bfloat16(v - __bfloat162float(h));
    } else {
        int q = idx - 2*WCONV_ELEMS;
        int i = q / WMLP_ELEMS, r = q % WMLP_ELEMS, n = r / C2, k = r % C2;
        float v = Ws.p[2 + i][k*C2 + n];
        __nv_bfloat16 h = __float2bfloat16(v);
        mhi[q] = h; mlo[q] = __float2bfloat16(v - __bfloat162float(h));
    }
}

// ---------------- fused TAGConv aggregate + activate + pool (R12 scalar) ------------
#define AGG_THREADS 512
template<bool L1>
__global__ void __launch_bounds__(AGG_THREADS)
tag_agg(const float* __restrict__ P, const float* __restrict__ x,
        const float* __restrict__ Wc, const int* __restrict__ knn,
        const float* __restrict__ bias,
        __nv_bfloat16* __restrict__ hhi, __nv_bfloat16* __restrict__ hlo,
        float* __restrict__ g, int layer) {
    extern __shared__ float sm[];
    float*   s2  = sm;
    float*   st  = sm + 8192;
    uint8_t* nbs = (uint8_t*)(sm + 16384);
    float*   xs  = (float*)(nbs + 3840);

    const int c0   = blockIdx.x*32;
    const int gph  = blockIdx.y;
    const int base = gph*MG;
    const int tid  = threadIdx.x;
    const int c    = tid & 31;
    const int ng   = tid >> 5;

    for (int i = tid; i < MG*KNN; i += AGG_THREADS)
        nbs[i] = (uint8_t)(knn[(size_t)base*KNN + i] & (MG-1));

    float w0[FIN], w1[FIN], w2[FIN];
    if (L1) {
#pragma unroll
        for (int f = 0; f < FIN; f++) {
            w0[f] = Wc[(0*FIN + f)*CC + c0 + c];
            w1[f] = Wc[(1*FIN + f)*CC + c0 + c];
            w2[f] = Wc[(2*FIN + f)*CC + c0 + c];
        }
        for (int i = tid; i < MG*FIN; i += AGG_THREADS)
            xs[(i/FIN)*8 + (i%FIN)] = x[(size_t)base*FIN + i];
    }

    if (L1) {
        __syncthreads();
#pragma unroll
        for (int j = 0; j < 16; j++) {
            int n = ng*16 + j;
            float acc = 0.0f;
#pragma unroll
            for (int f = 0; f < FIN; f++) acc += xs[n*8 + f]*w2[f];
            s2[n*32 + c] = acc;
        }
    } else {
#pragma unroll
        for (int j = 0; j < 16; j++) {
            int n = ng*16 + j;
            s2[n*32 + c] = P[(size_t)(base + n)*PST + 256 + c0 + c];
        }
    }
    __syncthreads();

#pragma unroll
    for (int j = 0; j < 16; j++) {
        int n = ng*16 + j;
        const uint8_t* nbp = nbs + n*KNN;
        float sa = 0.0f, sb = 0.0f;
#pragma unroll
        for (int k = 0; k < 14; k += 2) {
            sa += s2[(int)nbp[k]*32 + c];
            sb += s2[(int)nbp[k+1]*32 + c];
        }
        sa += s2[(int)nbp[14]*32 + c];
        float p1;
        if (L1) {
            p1 = 0.0f;
#pragma unroll
            for (int f = 0; f < FIN; f++) p1 += xs[n*8 + f]*w1[f];
        } else {
            p1 = P[(size_t)(base + n)*PST + 128 + c0 + c];
        }
        st[n*32 + c] = p1 + (sa + sb)*AGG_NORM;
    }
    __syncthreads();

    float bia = bias[c0 + c];
    float pm = 0.0f, px = -1e30f;
#pragma unroll
    for (int j = 0; j < 16; j++) {
        int n = ng*16 + j;
        const uint8_t* nbp = nbs + n*KNN;
        float sa = 0.0f, sb = 0.0f;
#pragma unroll
        for (int k = 0; k < 14; k += 2) {
            sa += st[(int)nbp[k]*32 + c];
            sb += st[(int)nbp[k+1]*32 + c];
        }
        sa += st[(int)nbp[14]*32 + c];
        float p0;
        if (L1) {
            p0 = 0.0f;
#pragma unroll
            for (int f = 0; f < FIN; f++) p0 += xs[n*8 + f]*w0[f];
        } else {
            p0 = P[(size_t)(base + n)*PST + c0 + c];
        }
        float v = p0 + (sa + sb)*AGG_NORM + bia;
        v = (v > 0.0f) ? v : LEAKY*v;
        __nv_bfloat16 vh = __float2bfloat16(v);
        hhi[(size_t)(base + n)*CC + c0 + c] = vh;
        hlo[(size_t)(base + n)*CC + c0 + c] = __float2bfloat16(v - __bfloat162float(vh));
        pm += v; px = fmaxf(px, v);
    }

    s2[ng*32 + c]        = pm;
    s2[1024 + ng*32 + c] = px;
    __syncthreads();
    if (ng == 0) {
        float m = 0.0f, xx = -1e30f;
#pragma unroll
        for (int q = 0; q < 16; q++) {
            m += s2[q*32 + c];
            xx = fmaxf(xx, s2[1024 + q*32 + c]);
        }
        g[gph*C2 + layer*256 + c0 + c]       = m*(1.0f/MG);
        g[gph*C2 + layer*256 + 128 + c0 + c] = xx;
    }
}
#define AGG_SMEM_MAIN (16384*4 + 3840)
#define AGG_SMEM_L1   (AGG_SMEM_MAIN + 2048*4)

// ---------------- cp.async 2-stage mma.sync bf16-split GEMM, KC=32 / 80B rows --------
// 80B rows: 16B aligned everywhere; r*80 mod 128 = {0,80,32,112,64,16,96,48} conflict-free.
#define KC    32
#define ROWB  80
template<int BM, int BN, int WM, int WN>
__global__ void __launch_bounds__(WM*WN*32)
mma_gemm(const __nv_bfloat16* __restrict__ Ahi, const __nv_bfloat16* __restrict__ Alo, int lda,
         const __nv_bfloat16* __restrict__ Bhi, const __nv_bfloat16* __restrict__ Blo, int ldb,
         int K, float* __restrict__ Cf, int ldc, size_t zstride) {
    constexpr int THREADS = WM*WN*32;
    constexpr int MT = BM/WM/16;
    constexpr int NT = BN/WN/8;
    constexpr int OF_AL = BM*ROWB;
    constexpr int OF_BH = 2*BM*ROWB;
    constexpr int OF_BL = 2*BM*ROWB + BN*ROWB;
    constexpr int STAGE = (2*BM + 2*BN)*ROWB;
    extern __shared__ char smc[];
    const uint32_t sb = smem_u32(smc);
    const int tid = threadIdx.x, wid = tid >> 5, lane = tid & 31;
    const int bm = blockIdx.y*BM, bn = blockIdx.x*BN;
    const int kbase = blockIdx.z*K;
    const int wm = wid % WM, wn = wid / WM;

    float acc[MT][NT][4] = {};

    auto prefetch = [&](int kc, int stage) {
        uint32_t base = sb + stage*STAGE;
        int k0 = kbase + kc*KC;
#pragma unroll
        for (int q = tid; q < BM*4; q += THREADS) {
            int r = q >> 2, c8 = q & 3;
            cpa16(base + r*ROWB + c8*16,          Ahi + (size_t)(bm + r)*lda + k0 + c8*8);
            cpa16(base + OF_AL + r*ROWB + c8*16,  Alo + (size_t)(bm + r)*lda + k0 + c8*8);
        }
#pragma unroll
        for (int q = tid; q < BN*4; q += THREADS) {
            int r = q >> 2, c8 = q & 3;
            cpa16(base + OF_BH + r*ROWB + c8*16,  Bhi + (size_t)(bn + r)*ldb + k0 + c8*8);
            cpa16(base + OF_BL + r*ROWB + c8*16,  Blo + (size_t)(bn + r)*ldb + k0 + c8*8);
        }
        cpa_commit();
    };

    const int ar = lane & 15, ac = (lane >> 4) << 3;
    const int l16 = lane & 15;
    const int br = l16 & 7, bc = (l16 >> 3) << 3;

    const int nk = K/KC;
    prefetch(0, 0);
    for (int kc = 0; kc < nk; kc++) {
        if (kc + 1 < nk) { prefetch(kc + 1, (kc + 1) & 1); cpa_wait1(); }
        else             { cpa_wait0(); }
        __syncthreads();
        uint32_t base = sb + (kc & 1)*STAGE;
#pragma unroll
        for (int kk = 0; kk < KC; kk += 16) {
            uint32_t ah[MT][4], al[MT][4], bh[NT][2], bl[NT][2];
#pragma unroll
            for (int mt = 0; mt < MT; mt++) {
                uint32_t off = (wm*(BM/WM) + mt*16 + ar)*ROWB + (kk + ac)*2;
                ldm_x4(ah[mt], base + off);
                ldm_x4(al[mt], base + OF_AL + off);
            }
#pragma unroll
            for (int nt = 0; nt < NT; nt++) {
                uint32_t off = (wn*(BN/WN) + nt*8 + br)*ROWB + (kk + bc)*2;
                ldm_x2(bh[nt], base + OF_BH + off);
                ldm_x2(bl[nt], base + OF_BL + off);
            }
#pragma unroll
            for (int mt = 0; mt < MT; mt++)
#pragma unroll
                for (int nt = 0; nt < NT; nt++) {
                    mma16816(acc[mt][nt], ah[mt], bh[nt]);
                    mma16816(acc[mt][nt], ah[mt], bl[nt]);
                    mma16816(acc[mt][nt], al[mt], bh[nt]);
                }
        }
        __syncthreads();
    }

    float* Co = Cf + (size_t)blockIdx.z*zstride;
    const int er = lane >> 2, ec = (lane & 3)*2;
#pragma unroll
    for (int mt = 0; mt < MT; mt++) {
#pragma unroll
        for (int nt = 0; nt < NT; nt++) {
            int row0 = bm + wm*(BM/WM) + mt*16 + er;
            int col0 = bn + wn*(BN/WN) + nt*8 + ec;
#pragma unroll
            for (int half = 0; half < 2; half++) {
                int row = row0 + half*8;
                float2 v = make_float2(acc[mt][nt][half*2 + 0], acc[mt][nt][half*2 + 1]);
                *reinterpret_cast<float2*>(&Co[(size_t)row*ldc + col0]) = v;
            }
        }
    }
}
#define GEMM_SMEM_CONV (2*(2*128 + 2*128)*ROWB)   // 81920 B -> 2 CTAs/SM
#define GEMM_SMEM_MLP  (2*(2*64 + 2*128)*ROWB)    // 61440 B -> 3 CTAs/SM

// ---------------- MLP finalize (float4 vectorized) ------------------------------------
__global__ void mlp_fin(const float4* __restrict__ part, const float* __restrict__ bias,
                        float4* __restrict__ gf,
                        uint2* __restrict__ ohi, uint2* __restrict__ olo) {
    int idx = blockIdx.x*256 + threadIdx.x;
    const int Q = NBATCH*C2/4;
    float4 a = part[idx], b = part[Q + idx], cpp = part[2*Q + idx], dd = part[3*Q + idx];
    int cb = (idx*4) % C2;
    float4 bi = *(const float4*)&bias[cb];
    float4 v;
    v.x = a.x + b.x + cpp.x + dd.x + bi.x;
    v.y = a.y + b.y + cpp.y + dd.y + bi.y;
    v.z = a.z + b.z + cpp.z + dd.z + bi.z;
    v.w = a.w + b.w + cpp.w + dd.w + bi.w;
    v.x = (v.x > 0.f) ? v.x : LEAKY*v.x;
    v.y = (v.y > 0.f) ? v.y : LEAKY*v.y;
    v.z = (v.z > 0.f) ? v.z : LEAKY*v.z;
    v.w = (v.w > 0.f) ? v.w : LEAKY*v.w;
    __nv_bfloat162 h01 = make_bfloat162(__float2bfloat16(v.x), __float2bfloat16(v.y));
    __nv_bfloat162 h23 = make_bfloat162(__float2bfloat16(v.z), __float2bfloat16(v.w));
    ohi[idx] = make_uint2(*(uint32_t*)&h01, *(uint32_t*)&h23);
    __nv_bfloat162 l01 = make_bfloat162(__float2bfloat16(v.x - __bfloat162float(h01.x)),
                                        __float2bfloat16(v.y - __bfloat162float(h01.y)));
    __nv_bfloat162 l23 = make_bfloat162(__float2bfloat16(v.z - __bfloat162float(h23.x)),
                                        __float2bfloat16(v.w - __bfloat162float(h23.y)));
    olo[idx] = make_uint2(*(uint32_t*)&l01, *(uint32_t*)&l23);
    if (gf) gf[idx] = v;
}

// ---------------- batch-norm -> bf16 split -----------------------------------------
__global__ void bn_kernel(const float* __restrict__ g, const float* __restrict__ gamma,
                          const float* __restrict__ beta,
                          __nv_bfloat16* __restrict__ ohi, __nv_bfloat16* __restrict__ olo) {
    __shared__ float red[256];
    int c = blockIdx.x, t = threadIdx.x;
    float v = g[t*C2 + c];
    red[t] = v; __syncthreads();
    for (int s = 128; s > 0; s >>= 1) { if (t < s) red[t] += red[t+s]; __syncthreads(); }
    float mu = red[0]*(1.0f/NBATCH);
    __syncthreads();
    float d = v - mu;
    red[t] = d*d; __syncthreads();
    for (int s = 128; s > 0; s >>= 1) { if (t < s) red[t] += red[t+s]; __syncthreads(); }
    float var = red[0]*(1.0f/NBATCH);
    float sc = rsqrtf(var + 1e-5f)*gamma[c];
    float o = (v - mu)*sc + beta[c];
    __nv_bfloat16 oh = __float2bfloat16(o);
    ohi[t*C2 + c] = oh;
    olo[t*C2 + c] = __float2bfloat16(o - __bfloat162float(oh));
}

// ---------------- head: (256,768)@(768,3) + tanh on cols 0,1 ------------------------
__global__ void head_kernel(const float* __restrict__ g, const float* __restrict__ Wo,
                            const float* __restrict__ bo, float* __restrict__ y) {
    int b = blockIdx.x;
    int w = threadIdx.y, l = threadIdx.x;
    float s = 0.0f;
    for (int f = l; f < C2; f += 32) s += g[b*C2 + f]*Wo[f*3 + w];
#pragma unroll
    for (int o = 16; o; o >>= 1) s += __shfl_down_sync(0xffffffff, s, o);
    if (l == 0) {
        float v = s + bo[w];
        if (w < 2) v = tanhf(v);
        y[b*3 + w] = v;
    }
}

// ---------------- launch --------------------------------------------------------------
extern "C" void kernel_launch(void* const* d_in, const int* in_sizes, int n_in,
                              void* d_out, int out_size) {
    const float* x   = (const float*)d_in[0];
    const float* Wc1 = (const float*)d_in[1];  const float* bc1 = (const float*)d_in[2];
    const float* Wc2 = (const float*)d_in[3];  const float* bc2 = (const float*)d_in[4];
    const float* Wc3 = (const float*)d_in[5];  const float* bc3 = (const float*)d_in[6];
    const float* bng = (const float*)d_in[7];  const float* bnb = (const float*)d_in[8];
    const float* Wm[5]; const float* bmv[5];
    for (int i = 0; i < 5; i++) { Wm[i] = (const float*)d_in[9+2*i]; bmv[i] = (const float*)d_in[10+2*i]; }
    const float* Wo = (const float*)d_in[19];  const float* bo = (const float*)d_in[20];
    float* y = (float*)d_out;

    int* knn; float *P, *pool, *gf, *part;
    __nv_bfloat16 *hhi, *hlo, *ghiA, *gloA, *ghiB, *gloB, *WctHi, *WctLo, *WmtHi, *WmtLo;
    cudaGetSymbolAddress((void**)&knn,  g_knn);
    cudaGetSymbolAddress((void**)&P,    g_P);
    cudaGetSymbolAddress((void**)&pool, g_pool);
    cudaGetSymbolAddress((void**)&gf,   g_gf);
    cudaGetSymbolAddress((void**)&part, g_part);
    cudaGetSymbolAddress((void**)&hhi,  g_hhi);
    cudaGetSymbolAddress((void**)&hlo,  g_hlo);
    cudaGetSymbolAddress((void**)&ghiA, g_ghiA);  cudaGetSymbolAddress((void**)&gloA, g_gloA);
    cudaGetSymbolAddress((void**)&ghiB, g_ghiB);  cudaGetSymbolAddress((void**)&gloB, g_gloB);
    cudaGetSymbolAddress((void**)&WctHi, g_WctHi); cudaGetSymbolAddress((void**)&WctLo, g_WctLo);
    cudaGetSymbolAddress((void**)&WmtHi, g_WmtHi); cudaGetSymbolAddress((void**)&WmtLo, g_WmtLo);

    cudaFuncSetAttribute(tag_agg<true>,  cudaFuncAttributeMaxDynamicSharedMemorySize, AGG_SMEM_L1);
    cudaFuncSetAttribute(tag_agg<false>, cudaFuncAttributeMaxDynamicSharedMemorySize, AGG_SMEM_MAIN);
    cudaFuncSetAttribute((const void*)mma_gemm<128,128,2,4>,
                         cudaFuncAttributeMaxDynamicSharedMemorySize, GEMM_SMEM_CONV);
    cudaFuncSetAttribute((const void*)mma_gemm<64,128,2,4>,
                         cudaFuncAttributeMaxDynamicSharedMemorySize, GEMM_SMEM_MLP);

    // 0. weight prep (single merged kernel)
    Ptr7 wall{ {Wc2, Wc3, Wm[0], Wm[1], Wm[2], Wm[3], Wm[4]} };
    wprep_all<<<(WPREP_TOTAL + 255)/256, 256>>>(wall, WctHi, WctLo, WmtHi, WmtLo);

    // 1. kNN (warp-per-node)
    knn_kernel<<<dim3(32, NBATCH), 256>>>(x, knn);

    // 2. layer 1 fused
    tag_agg<true><<<dim3(4, NBATCH), AGG_THREADS, AGG_SMEM_L1>>>(
        nullptr, x, Wc1, knn, bc1, hhi, hlo, pool, 0);

    // 3. layer 2
    mma_gemm<128,128,2,4><<<dim3(3, NTOT/128, 1), 256, GEMM_SMEM_CONV>>>(
        hhi, hlo, CC, WctHi, WctLo, CC, CC, P, PST, 0);
    tag_agg<false><<<dim3(4, NBATCH), AGG_THREADS, AGG_SMEM_MAIN>>>(
        P, nullptr, nullptr, knn, bc2, hhi, hlo, pool, 1);

    // 4. layer 3
    mma_gemm<128,128,2,4><<<dim3(3, NTOT/128, 1), 256, GEMM_SMEM_CONV>>>(
        hhi, hlo, CC, WctHi + 3*CC*CC, WctLo + 3*CC*CC, CC, CC, P, PST, 0);
    tag_agg<false><<<dim3(4, NBATCH), AGG_THREADS, AGG_SMEM_MAIN>>>(
        P, nullptr, nullptr, knn, bc3, hhi, hlo, pool, 2);

    // 5. batch-norm -> bf16 split
    bn_kernel<<<C2, 256>>>(pool, bng, bnb, ghiA, gloA);

    // 6. MLP x5: split-K x4 GEMM + finalize
    __nv_bfloat16 *chi = ghiA, *clo = gloA, *nhi = ghiB, *nlo = gloB;
    for (int i = 0; i < 5; i++) {
        mma_gemm<64,128,2,4><<<dim3(C2/128, NBATCH/64, 4), 256, GEMM_SMEM_MLP>>>(
            chi, clo, C2, WmtHi + (size_t)i*C2*C2, WmtLo + (size_t)i*C2*C2, C2,
            C2/4, part, C2, (size_t)NBATCH*C2);
        mlp_fin<<<NBATCH*C2/4/256, 256>>>((const float4*)part, bmv[i],
            (i == 4) ? (float4*)gf : nullptr, (uint2*)nhi, (uint2*)nlo);
        __nv_bfloat16* t1 = chi; chi = nhi; nhi = t1;
        __nv_bfloat16* t2 = clo; clo = nlo; nlo = t2;
    }

    // 7. head + fused tanh
    head_kernel<<<NBATCH, dim3(32, 3)>>>(gf, Wo, bo, y);
}